// round 13
// baseline (speedup 1.0000x reference)
#include <cuda_runtime.h>
#include <cuda_fp16.h>
#include <math.h>
#include <stdint.h>

// Problem constants
#define NE  160     // experts
#define CAP 120     // capacity per expert
#define NS  3200    // sequence length
#define NH  2048    // hidden dim
#define NI  192     // ffn dim per device
#define NK  6       // top-k

#define P   40      // fp32 smem pitch (floats); LDS.64 frag loads conflict-free
#define PB  80      // fp16 smem pitch (bytes) for down's resident A

#define STAGES 4                    // gateup cp.async ring depth
#define SSZ (320 * P)               // floats per stage: A(128*P)+Bg(96*P)+Bu(96*P)

// fp16 scratch (halves inter-kernel HBM traffic)
__device__ __half g_h[(size_t)NE * CAP * NI];   // 7.4 MB
__device__ __half g_o[(size_t)NE * CAP * NH];   // 79  MB

// single dynamic-shared symbol, cast per-kernel
extern __shared__ __align__(16) char dynsmem[];

// ---------------------------------------------------------------------------
// helpers
// ---------------------------------------------------------------------------
__device__ __forceinline__ uint32_t s2u(const void* p) {
    uint32_t a;
    asm("{ .reg .u64 t; cvta.to.shared.u64 t, %1; cvt.u32.u64 %0, t; }" : "=r"(a) : "l"(p));
    return a;
}
__device__ __forceinline__ void cp16(float* smem_dst, const float* gsrc) {
    uint32_t sa = (uint32_t)__cvta_generic_to_shared(smem_dst);
    asm volatile("cp.async.ca.shared.global [%0], [%1], 16;" :: "r"(sa), "l"(gsrc));
}
__device__ __forceinline__ void cp16s(uint32_t sa, const void* g) {
    asm volatile("cp.async.ca.shared.global [%0], [%1], 16;" :: "r"(sa), "l"(g));
}
__device__ __forceinline__ void cp_commit() { asm volatile("cp.async.commit_group;"); }
template<int N> __device__ __forceinline__ void cp_wait() {
    asm volatile("cp.async.wait_group %0;" :: "n"(N));
}
// pack float2 {lo,hi} -> f16x2 (lo in low 16 bits)
__device__ __forceinline__ uint32_t pk(float2 v) {
    uint32_t r;
    asm("cvt.rn.f16x2.f32 %0, %1, %2;" : "=r"(r) : "f"(v.y), "f"(v.x));
    return r;
}
__device__ __forceinline__ void ldm_x4(uint32_t* r, uint32_t a) {
    asm volatile("ldmatrix.sync.aligned.m8n8.x4.shared.b16 {%0,%1,%2,%3}, [%4];"
                 : "=r"(r[0]), "=r"(r[1]), "=r"(r[2]), "=r"(r[3]) : "r"(a));
}
__device__ __forceinline__ void mma_f16(float* c, const uint32_t* a, const uint32_t* b) {
    asm volatile(
        "mma.sync.aligned.m16n8k16.row.col.f32.f16.f16.f32 "
        "{%0,%1,%2,%3},{%4,%5,%6,%7},{%8,%9},{%0,%1,%2,%3};"
        : "+f"(c[0]), "+f"(c[1]), "+f"(c[2]), "+f"(c[3])
        : "r"(a[0]), "r"(a[1]), "r"(a[2]), "r"(a[3]), "r"(b[0]), "r"(b[1]));
}
__device__ __forceinline__ float silu(float g) { return g / (1.f + __expf(-g)); }
__device__ __forceinline__ float2 ld2(const float* p) { return *(const float2*)p; }

// ---------------------------------------------------------------------------
// Kernel 1: gathered gate/up GEMM (fp16 MMA, fp32 accum) + fused SiLU
//   grid = (2 I-halves of 96, NE) = 320 blocks. 256 thr, 8 warps (wm4 x wn2).
//   Block tile M=128 x N=96 for BOTH gate and up; warp tile 32x48 per matrix.
//   K chunk 32 (2 k16 steps). 4-stage cp.async ring (3 chunks in flight),
//   ONE __syncthreads per chunk. Frags packed fp32->fp16 at the register edge.
// ---------------------------------------------------------------------------
__global__ __launch_bounds__(256) void k_gateup(
    const float* __restrict__ hs,   // [S,H]
    const int*   __restrict__ tok,  // [E,CAP]
    const float* __restrict__ gw,   // [E,I,H]
    const float* __restrict__ uw)   // [E,I,H]
{
    float* smem = (float*)dynsmem;  // [STAGES][SSZ]

    const int e   = blockIdx.y;
    const int i0  = blockIdx.x * 96;
    const int tid = threadIdx.x;
    const int w   = tid >> 5, lane = tid & 31;
    const int wm  = w >> 1, wn = w & 1;
    const int gr  = lane >> 2, tg = lane & 3;

    __shared__ int toks[128];
    if (tid < CAP)      toks[tid] = tok[e * CAP + tid];
    else if (tid < 128) toks[tid] = tok[e * CAP + CAP - 1];
    __syncthreads();

    const float* gwe = gw + ((size_t)e * NI + i0) * NH;
    const float* uwe = uw + ((size_t)e * NI + i0) * NH;

    float accg[2][6][4] = {};
    float accu[2][6][4] = {};

    const int NC = NH / 32;        // 64 chunks

    auto load_chunk = [&](int stage, int kc) {
        const int k0 = kc * 32;
        float* Ab = smem + stage * SSZ;
        float* Gb = Ab + 128 * P;
        float* Ub = Gb + 96 * P;
#pragma unroll
        for (int p = 0; p < 4; p++) {           // A: 128 rows x 8 f4
            int idx = tid + p * 256;
            int r = idx >> 3, c4 = (idx & 7) << 2;
            cp16(Ab + r * P + c4, hs + (size_t)toks[r] * NH + k0 + c4);
        }
#pragma unroll
        for (int p = 0; p < 3; p++) {           // Bg: 96 x 8 f4
            int idx = tid + p * 256;
            int r = idx >> 3, c4 = (idx & 7) << 2;
            cp16(Gb + r * P + c4, gwe + (size_t)r * NH + k0 + c4);
        }
#pragma unroll
        for (int p = 0; p < 3; p++) {           // Bu: 96 x 8 f4
            int idx = tid + p * 256;
            int r = idx >> 3, c4 = (idx & 7) << 2;
            cp16(Ub + r * P + c4, uwe + (size_t)r * NH + k0 + c4);
        }
        cp_commit();
    };

    // prologue: stages 0..2 <- chunks 0..2 (3 groups in flight)
    load_chunk(0, 0);
    load_chunk(1, 1);
    load_chunk(2, 2);

    for (int kc = 0; kc < NC; kc++) {
        // drain so chunk kc has arrived (stepped in the tail)
        if (kc < NC - 2)      cp_wait<2>();
        else if (kc == NC - 2) cp_wait<1>();
        else                   cp_wait<0>();
        __syncthreads();   // chunk kc visible to all; all warps done with kc-1

        // refill the stage freed at kc-1 with chunk kc+3
        if (kc + STAGES - 1 < NC) load_chunk((kc + STAGES - 1) & 3, kc + STAGES - 1);

        const float* Sb = smem + (kc & 3) * SSZ;
        const float* A  = Sb + wm * 32 * P;
        const float* BG = Sb + 128 * P + wn * 48 * P;
        const float* BU = Sb + (128 + 96) * P + wn * 48 * P;

#pragma unroll
        for (int ks = 0; ks < 2; ks++) {
            const int c0 = ks * 16 + 2 * tg;
            uint32_t a0[4], a1[4];
            a0[0] = pk(ld2(&A[(gr     ) * P + c0    ]));
            a0[1] = pk(ld2(&A[(gr +  8) * P + c0    ]));
            a0[2] = pk(ld2(&A[(gr     ) * P + c0 + 8]));
            a0[3] = pk(ld2(&A[(gr +  8) * P + c0 + 8]));
            a1[0] = pk(ld2(&A[(gr + 16) * P + c0    ]));
            a1[1] = pk(ld2(&A[(gr + 24) * P + c0    ]));
            a1[2] = pk(ld2(&A[(gr + 16) * P + c0 + 8]));
            a1[3] = pk(ld2(&A[(gr + 24) * P + c0 + 8]));
#pragma unroll
            for (int nt = 0; nt < 6; nt++) {
                uint32_t b[2];
                b[0] = pk(ld2(&BG[(nt * 8 + gr) * P + c0    ]));
                b[1] = pk(ld2(&BG[(nt * 8 + gr) * P + c0 + 8]));
                mma_f16(accg[0][nt], a0, b);
                mma_f16(accg[1][nt], a1, b);
                b[0] = pk(ld2(&BU[(nt * 8 + gr) * P + c0    ]));
                b[1] = pk(ld2(&BU[(nt * 8 + gr) * P + c0 + 8]));
                mma_f16(accu[0][nt], a0, b);
                mma_f16(accu[1][nt], a1, b);
            }
        }
    }

    // Epilogue: h = silu(g)*u -> g_h (fp16)
#pragma unroll
    for (int mt = 0; mt < 2; mt++) {
#pragma unroll
        for (int half = 0; half < 2; half++) {
            const int r = wm * 32 + mt * 16 + gr + half * 8;
            if (r < CAP) {
                __half* dst = g_h + ((size_t)e * CAP + r) * NI + i0 + wn * 48;
#pragma unroll
                for (int nt = 0; nt < 6; nt++) {
                    float g0 = accg[mt][nt][half * 2 + 0];
                    float g1 = accg[mt][nt][half * 2 + 1];
                    float u0 = accu[mt][nt][half * 2 + 0];
                    float u1 = accu[mt][nt][half * 2 + 1];
                    *(__half2*)(dst + nt * 8 + 2 * tg) =
                        __floats2half2_rn(silu(g0) * u0, silu(g1) * u1);
                }
            }
        }
    }
}

// ---------------------------------------------------------------------------
// Kernel 2: down projection. A resident fp16 (ldmatrix), B streamed fp32
//   via cp.async + fragment pack. grid (16 H-tiles of 128, NE), 256 thr.
//   Block tile M=128 x N=128, K=192; warp 32x64. 2 CTAs/SM.
// ---------------------------------------------------------------------------
__global__ __launch_bounds__(256, 2) void k_down(const float* __restrict__ dw /*[E,H,I]*/)
{
    const uint32_t sb = s2u(dynsmem);
    const uint32_t sA = sb;                      // 6 x 128*PB = 61440 (fp16)
    float* Bs = (float*)(dynsmem + 61440);       // [2][128*P] fp32 = 40960

    const int e   = blockIdx.y;
    const int h0  = blockIdx.x * 128;
    const int tid = threadIdx.x;
    const int w   = tid >> 5, lane = tid & 31;
    const int wm  = w >> 1, wn = w & 1;
    const int gr  = lane >> 2, tg = lane & 3;
    const int lrow = lane & 7, lsel = lane >> 3;

    // Preload whole A: [6][128 rows][4 x 16B] fp16 from g_h
    const __half* hsrc = g_h + (size_t)e * CAP * NI;
#pragma unroll
    for (int p = 0; p < 12; p++) {
        int idx = tid + p * 256;                 // 3072
        int kc = idx >> 9, rem = idx & 511, r = rem >> 2, c = rem & 3;
        int rr = r < CAP ? r : CAP - 1;
        cp16s(sA + kc * (128 * PB) + r * PB + c * 16,
              hsrc + (size_t)rr * NI + kc * 32 + c * 8);
    }
    cp_commit();                                 // group: A

    const float* dwe = dw + ((size_t)e * NH + h0) * NI;
    auto loadB = [&](int buf, int kc) {
        const int k0 = kc * 32;
        float* Bb = Bs + buf * 128 * P;
#pragma unroll
        for (int p = 0; p < 4; p++) {            // 128 rows x 8 f4
            int idx = tid + p * 256;
            int r = idx >> 3, c4 = (idx & 7) << 2;
            cp16(Bb + r * P + c4, dwe + (size_t)r * NI + k0 + c4);
        }
        cp_commit();
    };

    // A ldmatrix lane offset (bytes within a chunk-tile)
    const uint32_t aoff = (uint32_t)((wm * 32 + lrow + ((lsel & 1) << 3)) * PB + ((lsel >> 1) << 4));

    float acc[2][8][4] = {};

    loadB(0, 0);
    int buf = 0;
    for (int kc = 0; kc < 6; kc++) {
        if (kc + 1 < 6) { loadB(buf ^ 1, kc + 1); cp_wait<1>(); }
        else           { cp_wait<0>(); }
        __syncthreads();

        const uint32_t Ab = sA + kc * (128 * PB);
        const float* B = Bs + buf * 128 * P + wn * 64 * P;

#pragma unroll
        for (int ks = 0; ks < 2; ks++) {
            const uint32_t kb = (uint32_t)(ks * 32);   // 16 halves
            const int c0 = ks * 16 + 2 * tg;
            uint32_t a0[4], a1[4];
            ldm_x4(a0, Ab + aoff + kb);
            ldm_x4(a1, Ab + aoff + 16 * PB + kb);
#pragma unroll
            for (int nt = 0; nt < 8; nt++) {
                uint32_t b[2];
                b[0] = pk(ld2(&B[(nt * 8 + gr) * P + c0    ]));
                b[1] = pk(ld2(&B[(nt * 8 + gr) * P + c0 + 8]));
                mma_f16(acc[0][nt], a0, b);
                mma_f16(acc[1][nt], a1, b);
            }
        }
        __syncthreads();
        buf ^= 1;
    }

    // Epilogue -> g_o (fp16)
#pragma unroll
    for (int mt = 0; mt < 2; mt++) {
#pragma unroll
        for (int half = 0; half < 2; half++) {
            const int r = wm * 32 + mt * 16 + gr + half * 8;
            if (r < CAP) {
                __half* dst = g_o + ((size_t)e * CAP + r) * NH + h0 + wn * 64;
#pragma unroll
                for (int nt = 0; nt < 8; nt++) {
                    *(__half2*)(dst + nt * 8 + 2 * tg) =
                        __floats2half2_rn(acc[mt][nt][half * 2 + 0],
                                          acc[mt][nt][half * 2 + 1]);
                }
            }
        }
    }
}

// ---------------------------------------------------------------------------
// Kernel 3: permute-gather + top-k weighted combine + shared expert
// ---------------------------------------------------------------------------
__global__ __launch_bounds__(256) void k_combine(
    const int*   __restrict__ rei,  // [K*S]
    const float* __restrict__ tw,   // [K,S,1]
    const float* __restrict__ sh,   // [1,S,H]
    float*       __restrict__ out)  // [1,S,H]
{
    const int s = blockIdx.x;
    __shared__ int   rows[NK];
    __shared__ float wts[NK];
    if (threadIdx.x < NK) {
        rows[threadIdx.x] = rei[threadIdx.x * NS + s];
        wts[threadIdx.x]  = tw[threadIdx.x * NS + s];
    }
    __syncthreads();

    for (int h = threadIdx.x * 4; h < NH; h += 256 * 4) {
        float4 a = *(const float4*)(sh + (size_t)s * NH + h);
#pragma unroll
        for (int k = 0; k < NK; k++) {
            const __half* src = g_o + (size_t)rows[k] * NH + h;
            float2 f01 = __half22float2(*(const __half2*)(src));
            float2 f23 = __half22float2(*(const __half2*)(src + 2));
            const float wv = wts[k];
            a.x = fmaf(wv, f01.x, a.x);
            a.y = fmaf(wv, f01.y, a.y);
            a.z = fmaf(wv, f23.x, a.z);
            a.w = fmaf(wv, f23.y, a.w);
        }
        *(float4*)(out + (size_t)s * NH + h) = a;
    }
}

// ---------------------------------------------------------------------------
extern "C" void kernel_launch(void* const* d_in, const int* in_sizes, int n_in,
                              void* d_out, int out_size)
{
    const float* hs  = (const float*)d_in[0];
    const int*   tok = (const int*)  d_in[1];
    const int*   rei = (const int*)  d_in[2];
    const float* tw  = (const float*)d_in[3];
    const float* sh  = (const float*)d_in[4];
    const float* gw  = (const float*)d_in[5];
    const float* uw  = (const float*)d_in[6];
    const float* dw  = (const float*)d_in[7];
    float* out = (float*)d_out;

    const int smem1 = STAGES * SSZ * 4;               // 204800 B
    const int smem2 = 6 * 128 * PB + 2 * 128 * P * 4; // 102400 B
    cudaFuncSetAttribute(k_gateup, cudaFuncAttributeMaxDynamicSharedMemorySize, smem1);
    cudaFuncSetAttribute(k_down,   cudaFuncAttributeMaxDynamicSharedMemorySize, smem2);

    dim3 g1(2, NE);         // 320 blocks
    k_gateup<<<g1, 256, smem1>>>(hs, tok, gw, uw);

    dim3 g2(NH / 128, NE);  // 2560 blocks
    k_down<<<g2, 256, smem2>>>(dw);

    k_combine<<<NS, 256>>>(rei, tw, sh, out);
}

// round 14
// speedup vs baseline: 1.1116x; 1.1116x over previous
#include <cuda_runtime.h>
#include <cuda_fp16.h>
#include <math.h>
#include <stdint.h>

// Problem constants
#define NE  160     // experts
#define CAP 120     // capacity per expert
#define NS  3200    // sequence length
#define NH  2048    // hidden dim
#define NI  192     // ffn dim per device
#define NK  6       // top-k

#define P   40      // fp32 smem pitch (floats); LDS.64 frag loads conflict-free

#define GU_STAGES 3
#define GU_SSZ ((128 + 48 + 48) * P)   // floats per gateup stage = 8960 (35840 B)

// Scratch: h fp32 (R7-exact down input), o fp16 (halves down-write+combine-read)
__device__ float  g_h[(size_t)NE * CAP * NI];   // 14.7 MB
__device__ __half g_o[(size_t)NE * CAP * NH];   // 79   MB

// single dynamic-shared symbol, cast per-kernel
extern __shared__ __align__(16) char dynsmem[];

// ---------------------------------------------------------------------------
// helpers
// ---------------------------------------------------------------------------
__device__ __forceinline__ void cp16(float* smem_dst, const float* gsrc) {
    uint32_t sa = (uint32_t)__cvta_generic_to_shared(smem_dst);
    asm volatile("cp.async.ca.shared.global [%0], [%1], 16;" :: "r"(sa), "l"(gsrc));
}
__device__ __forceinline__ void cp_commit() { asm volatile("cp.async.commit_group;"); }
template<int N> __device__ __forceinline__ void cp_wait() {
    asm volatile("cp.async.wait_group %0;" :: "n"(N));
}
// pack float2 {lo,hi} -> f16x2 (lo in low 16 bits)
__device__ __forceinline__ uint32_t pk(float2 v) {
    uint32_t r;
    asm("cvt.rn.f16x2.f32 %0, %1, %2;" : "=r"(r) : "f"(v.y), "f"(v.x));
    return r;
}
__device__ __forceinline__ void mma_f16(float* c, const uint32_t* a, const uint32_t* b) {
    asm volatile(
        "mma.sync.aligned.m16n8k16.row.col.f32.f16.f16.f32 "
        "{%0,%1,%2,%3},{%4,%5,%6,%7},{%8,%9},{%0,%1,%2,%3};"
        : "+f"(c[0]), "+f"(c[1]), "+f"(c[2]), "+f"(c[3])
        : "r"(a[0]), "r"(a[1]), "r"(a[2]), "r"(a[3]), "r"(b[0]), "r"(b[1]));
}
__device__ __forceinline__ float silu(float g) { return g / (1.f + __expf(-g)); }
__device__ __forceinline__ float2 ld2(const float* p) { return *(const float2*)p; }

// ---------------------------------------------------------------------------
// Kernel 1: gathered gate/up GEMM (fp16 MMA, fp32 accum) + fused SiLU
//   grid = (4 I-tiles of 48, NE) = 640 blocks. 256 thr (8 warps: wm4 x wn2).
//   Block tile M=128 x N=48 for BOTH gate and up; warp tile 32x24 per matrix.
//   K chunk 32 (2 k16 steps). 3-stage cp.async ring (2 chunks ahead),
//   ONE __syncthreads per chunk, 2 CTAs/SM.
// ---------------------------------------------------------------------------
__global__ __launch_bounds__(256, 2) void k_gateup(
    const float* __restrict__ hs,   // [S,H]
    const int*   __restrict__ tok,  // [E,CAP]
    const float* __restrict__ gw,   // [E,I,H]
    const float* __restrict__ uw)   // [E,I,H]
{
    float* smem = (float*)dynsmem;  // [GU_STAGES][GU_SSZ]

    const int e   = blockIdx.y;
    const int i0  = blockIdx.x * 48;
    const int tid = threadIdx.x;
    const int w   = tid >> 5, lane = tid & 31;
    const int wm  = w >> 1, wn = w & 1;
    const int gr  = lane >> 2, tg = lane & 3;

    __shared__ int toks[128];
    if (tid < CAP)      toks[tid] = tok[e * CAP + tid];
    else if (tid < 128) toks[tid] = tok[e * CAP + CAP - 1];
    __syncthreads();

    const float* gwe = gw + ((size_t)e * NI + i0) * NH;
    const float* uwe = uw + ((size_t)e * NI + i0) * NH;

    float accg[2][3][4] = {};
    float accu[2][3][4] = {};

    const int NC = NH / 32;        // 64 chunks

    auto load_chunk = [&](int stage, int kc) {
        const int k0 = kc * 32;
        float* Ab = smem + stage * GU_SSZ;
        float* Gb = Ab + 128 * P;
        float* Ub = Gb + 48 * P;
#pragma unroll
        for (int p = 0; p < 4; p++) {           // A: 128 rows x 8 f4
            int idx = tid + p * 256;
            int r = idx >> 3, c4 = (idx & 7) << 2;
            cp16(Ab + r * P + c4, hs + (size_t)toks[r] * NH + k0 + c4);
        }
#pragma unroll
        for (int p = 0; p < 3; p++) {           // Bg+Bu: 2 x 48 x 8 f4 = 768
            int idx = tid + p * 256;
            if (idx < 384) {
                int r = idx >> 3, c4 = (idx & 7) << 2;
                cp16(Gb + r * P + c4, gwe + (size_t)r * NH + k0 + c4);
            } else {
                int j = idx - 384;
                int r = j >> 3, c4 = (j & 7) << 2;
                cp16(Ub + r * P + c4, uwe + (size_t)r * NH + k0 + c4);
            }
        }
        cp_commit();
    };

    // prologue: 2 chunks in flight
    load_chunk(0, 0);
    load_chunk(1, 1);

    for (int kc = 0; kc < NC; kc++) {
        // ensure chunk kc has landed. Pending just before here:
        //   {kc, kc+1} in steady state -> wait<1>; last iter only {kc} -> wait<0>.
        if (kc == NC - 1) cp_wait<0>();
        else              cp_wait<1>();
        __syncthreads();   // kc visible everywhere; all warps done computing kc-1

        // refill the stage chunk kc-1 occupied ((kc+2)%3 == (kc-1)%3)
        if (kc + 2 < NC) load_chunk((kc + 2) % 3, kc + 2);

        const float* Sb = smem + (kc % 3) * GU_SSZ;
        const float* A  = Sb + wm * 32 * P;
        const float* BG = Sb + 128 * P + wn * 24 * P;
        const float* BU = Sb + (128 + 48) * P + wn * 24 * P;

#pragma unroll
        for (int ks = 0; ks < 2; ks++) {
            const int c0 = ks * 16 + 2 * tg;
            uint32_t a0[4], a1[4];
            a0[0] = pk(ld2(&A[(gr     ) * P + c0    ]));
            a0[1] = pk(ld2(&A[(gr +  8) * P + c0    ]));
            a0[2] = pk(ld2(&A[(gr     ) * P + c0 + 8]));
            a0[3] = pk(ld2(&A[(gr +  8) * P + c0 + 8]));
            a1[0] = pk(ld2(&A[(gr + 16) * P + c0    ]));
            a1[1] = pk(ld2(&A[(gr + 24) * P + c0    ]));
            a1[2] = pk(ld2(&A[(gr + 16) * P + c0 + 8]));
            a1[3] = pk(ld2(&A[(gr + 24) * P + c0 + 8]));
#pragma unroll
            for (int nt = 0; nt < 3; nt++) {
                uint32_t b[2];
                b[0] = pk(ld2(&BG[(nt * 8 + gr) * P + c0    ]));
                b[1] = pk(ld2(&BG[(nt * 8 + gr) * P + c0 + 8]));
                mma_f16(accg[0][nt], a0, b);
                mma_f16(accg[1][nt], a1, b);
                b[0] = pk(ld2(&BU[(nt * 8 + gr) * P + c0    ]));
                b[1] = pk(ld2(&BU[(nt * 8 + gr) * P + c0 + 8]));
                mma_f16(accu[0][nt], a0, b);
                mma_f16(accu[1][nt], a1, b);
            }
        }
    }

    // Epilogue: h = silu(g)*u -> g_h (fp32)
#pragma unroll
    for (int mt = 0; mt < 2; mt++) {
#pragma unroll
        for (int half = 0; half < 2; half++) {
            const int r = wm * 32 + mt * 16 + gr + half * 8;
            if (r < CAP) {
                float* dst = g_h + ((size_t)e * CAP + r) * NI + i0 + wn * 24;
#pragma unroll
                for (int nt = 0; nt < 3; nt++) {
                    float g0 = accg[mt][nt][half * 2 + 0];
                    float g1 = accg[mt][nt][half * 2 + 1];
                    float u0 = accu[mt][nt][half * 2 + 0];
                    float u1 = accu[mt][nt][half * 2 + 1];
                    float2 hv = make_float2(silu(g0) * u0, silu(g1) * u1);
                    *(float2*)(dst + nt * 8 + 2 * tg) = hv;
                }
            }
        }
    }
}

// ---------------------------------------------------------------------------
// Kernel 2: down projection (fp16 MMA via pk fragments, fp32 smem, R7-exact)
//   o[e,c,h] = sum_i h[e,c,i] * down_w[e,h,i]   -> g_o (fp16)
//   grid = (16 H-tiles of 128, NE). Block tile M=128 x N=128, K=192.
//   8 warps: 4 along M x 2 along N -> warp 32x64. 2 CTAs/SM.
// ---------------------------------------------------------------------------
__global__ __launch_bounds__(256, 2) void k_down(const float* __restrict__ dw /*[E,H,I]*/)
{
    float* smem = (float*)dynsmem;
    float* As = smem;               // [2][128*P]
    float* Bs = As + 2 * 128 * P;   // [2][128*P]

    const int e   = blockIdx.y;
    const int h0  = blockIdx.x * 128;
    const int tid = threadIdx.x;
    const int w   = tid >> 5, lane = tid & 31;
    const int wm  = w >> 1, wn = w & 1;
    const int gr  = lane >> 2, tg = lane & 3;

    const float* hsrc = g_h + (size_t)e * CAP * NI;
    const float* dwe  = dw + ((size_t)e * NH + h0) * NI;

    float acc[2][8][4] = {};

    const int NC = NI / 32;    // 6 chunks

    auto load_chunk = [&](int buf, int kc) {
        const int k0 = kc * 32;
        float* Ab = As + buf * 128 * P;
        float* Bb = Bs + buf * 128 * P;
#pragma unroll
        for (int p = 0; p < 4; p++) {           // A: 128 x 8 f4 (rows>=CAP clamped)
            int idx = tid + p * 256;
            int r = idx >> 3, c4 = (idx & 7) << 2;
            int rr = r < CAP ? r : CAP - 1;
            cp16(Ab + r * P + c4, hsrc + (size_t)rr * NI + k0 + c4);
        }
#pragma unroll
        for (int p = 0; p < 4; p++) {           // B: 128 x 8 f4
            int idx = tid + p * 256;
            int r = idx >> 3, c4 = (idx & 7) << 2;
            cp16(Bb + r * P + c4, dwe + (size_t)r * NI + k0 + c4);
        }
        cp_commit();
    };

    load_chunk(0, 0);

    int buf = 0;
    for (int kc = 0; kc < NC; kc++) {
        if (kc + 1 < NC) {
            load_chunk(buf ^ 1, kc + 1);
            cp_wait<1>();
        } else {
            cp_wait<0>();
        }
        __syncthreads();

        const float* A = As + buf * 128 * P + wm * 32 * P;
        const float* B = Bs + buf * 128 * P + wn * 64 * P;

#pragma unroll
        for (int ks = 0; ks < 2; ks++) {
            const int c0 = ks * 16 + 2 * tg;
            uint32_t a0[4], a1[4];
            a0[0] = pk(ld2(&A[(gr     ) * P + c0    ]));
            a0[1] = pk(ld2(&A[(gr +  8) * P + c0    ]));
            a0[2] = pk(ld2(&A[(gr     ) * P + c0 + 8]));
            a0[3] = pk(ld2(&A[(gr +  8) * P + c0 + 8]));
            a1[0] = pk(ld2(&A[(gr + 16) * P + c0    ]));
            a1[1] = pk(ld2(&A[(gr + 24) * P + c0    ]));
            a1[2] = pk(ld2(&A[(gr + 16) * P + c0 + 8]));
            a1[3] = pk(ld2(&A[(gr + 24) * P + c0 + 8]));
#pragma unroll
            for (int nt = 0; nt < 8; nt++) {
                uint32_t b[2];
                b[0] = pk(ld2(&B[(nt * 8 + gr) * P + c0    ]));
                b[1] = pk(ld2(&B[(nt * 8 + gr) * P + c0 + 8]));
                mma_f16(acc[0][nt], a0, b);
                mma_f16(acc[1][nt], a1, b);
            }
        }
        __syncthreads();
        buf ^= 1;
    }

    // Epilogue -> g_o (fp16)
#pragma unroll
    for (int mt = 0; mt < 2; mt++) {
#pragma unroll
        for (int half = 0; half < 2; half++) {
            const int r = wm * 32 + mt * 16 + gr + half * 8;
            if (r < CAP) {
                __half* dst = g_o + ((size_t)e * CAP + r) * NH + h0 + wn * 64;
#pragma unroll
                for (int nt = 0; nt < 8; nt++) {
                    *(__half2*)(dst + nt * 8 + 2 * tg) =
                        __floats2half2_rn(acc[mt][nt][half * 2 + 0],
                                          acc[mt][nt][half * 2 + 1]);
                }
            }
        }
    }
}

// ---------------------------------------------------------------------------
// Kernel 3: permute-gather + top-k weighted combine + shared expert
// ---------------------------------------------------------------------------
__global__ __launch_bounds__(256) void k_combine(
    const int*   __restrict__ rei,  // [K*S]
    const float* __restrict__ tw,   // [K,S,1]
    const float* __restrict__ sh,   // [1,S,H]
    float*       __restrict__ out)  // [1,S,H]
{
    const int s = blockIdx.x;
    __shared__ int   rows[NK];
    __shared__ float wts[NK];
    if (threadIdx.x < NK) {
        rows[threadIdx.x] = rei[threadIdx.x * NS + s];
        wts[threadIdx.x]  = tw[threadIdx.x * NS + s];
    }
    __syncthreads();

    for (int h = threadIdx.x * 4; h < NH; h += 256 * 4) {
        float4 a = *(const float4*)(sh + (size_t)s * NH + h);
#pragma unroll
        for (int k = 0; k < NK; k++) {
            const __half* src = g_o + (size_t)rows[k] * NH + h;
            float2 f01 = __half22float2(*(const __half2*)(src));
            float2 f23 = __half22float2(*(const __half2*)(src + 2));
            const float wv = wts[k];
            a.x = fmaf(wv, f01.x, a.x);
            a.y = fmaf(wv, f01.y, a.y);
            a.z = fmaf(wv, f23.x, a.z);
            a.w = fmaf(wv, f23.y, a.w);
        }
        *(float4*)(out + (size_t)s * NH + h) = a;
    }
}

// ---------------------------------------------------------------------------
extern "C" void kernel_launch(void* const* d_in, const int* in_sizes, int n_in,
                              void* d_out, int out_size)
{
    const float* hs  = (const float*)d_in[0];
    const int*   tok = (const int*)  d_in[1];
    const int*   rei = (const int*)  d_in[2];
    const float* tw  = (const float*)d_in[3];
    const float* sh  = (const float*)d_in[4];
    const float* gw  = (const float*)d_in[5];
    const float* uw  = (const float*)d_in[6];
    const float* dw  = (const float*)d_in[7];
    float* out = (float*)d_out;

    const int smem1 = GU_STAGES * GU_SSZ * 4;   // 107520 B  (2 CTAs/SM = 215 KB)
    const int smem2 = 2 * (128 + 128) * P * 4;  // 81920 B
    cudaFuncSetAttribute(k_gateup, cudaFuncAttributeMaxDynamicSharedMemorySize, smem1);
    cudaFuncSetAttribute(k_down,   cudaFuncAttributeMaxDynamicSharedMemorySize, smem2);

    dim3 g1(4, NE);         // 640 blocks
    k_gateup<<<g1, 256, smem1>>>(hs, tok, gw, uw);

    dim3 g2(NH / 128, NE);  // 2560 blocks
    k_down<<<g2, 256, smem2>>>(dw);

    k_combine<<<NS, 256>>>(rei, tw, sh, out);
}

// round 16
// speedup vs baseline: 1.4082x; 1.2668x over previous
#include <cuda_runtime.h>
#include <cuda_fp16.h>
#include <math.h>
#include <stdint.h>

// Problem constants
#define NE  160     // experts
#define CAP 120     // capacity per expert
#define NS  3200    // sequence length
#define NH  2048    // hidden dim
#define NI  192     // ffn dim per device
#define NK  6       // top-k

#define P   40      // fp32 smem pitch (floats); LDS.64 frag loads conflict-free

// Scratch: h fp32 (R7-exact down input), o fp16 (halves down-write+combine-read)
__device__ float  g_h[(size_t)NE * CAP * NI];   // 14.7 MB
__device__ __half g_o[(size_t)NE * CAP * NH];   // 79   MB

// ---------------------------------------------------------------------------
// helpers
// ---------------------------------------------------------------------------
__device__ __forceinline__ void cp16(float* smem_dst, const float* gsrc) {
    uint32_t sa = (uint32_t)__cvta_generic_to_shared(smem_dst);
    // .cg: L2-only. All tiles are streaming (zero reuse) -> keep L1 clean.
    asm volatile("cp.async.cg.shared.global [%0], [%1], 16;" :: "r"(sa), "l"(gsrc));
}
__device__ __forceinline__ void cp_commit() { asm volatile("cp.async.commit_group;"); }
template<int N> __device__ __forceinline__ void cp_wait() {
    asm volatile("cp.async.wait_group %0;" :: "n"(N));
}
// pack float2 {lo,hi} -> f16x2 (lo in low 16 bits)
__device__ __forceinline__ uint32_t pk(float2 v) {
    uint32_t r;
    asm("cvt.rn.f16x2.f32 %0, %1, %2;" : "=r"(r) : "f"(v.y), "f"(v.x));
    return r;
}
__device__ __forceinline__ void mma_f16(float* c, const uint32_t* a, const uint32_t* b) {
    asm volatile(
        "mma.sync.aligned.m16n8k16.row.col.f32.f16.f16.f32 "
        "{%0,%1,%2,%3},{%4,%5,%6,%7},{%8,%9},{%0,%1,%2,%3};"
        : "+f"(c[0]), "+f"(c[1]), "+f"(c[2]), "+f"(c[3])
        : "r"(a[0]), "r"(a[1]), "r"(a[2]), "r"(a[3]), "r"(b[0]), "r"(b[1]));
}
__device__ __forceinline__ float silu(float g) { return g / (1.f + __expf(-g)); }
__device__ __forceinline__ float2 ld2(const float* p) { return *(const float2*)p; }

// ---------------------------------------------------------------------------
// Kernel 1: gathered gate/up GEMM (fp16 MMA, fp32 accum) + fused SiLU
//   R7-exact geometry: grid (4 I-tiles of 48, NE), 256 thr (8 warps wm4 x wn2),
//   block tile M=128 x N=48 for BOTH gate and up, K chunk 32 (2 k16 steps),
//   2-stage cp.async pipeline, 2 CTAs/SM.
// ---------------------------------------------------------------------------
__global__ __launch_bounds__(256, 2) void k_gateup(
    const float* __restrict__ hs,   // [S,H]
    const int*   __restrict__ tok,  // [E,CAP]
    const float* __restrict__ gw,   // [E,I,H]
    const float* __restrict__ uw)   // [E,I,H]
{
    extern __shared__ float smem[];
    float* As = smem;               // [2][128*P]
    float* Bg = As + 2 * 128 * P;   // [2][48*P]
    float* Bu = Bg + 2 * 48 * P;    // [2][48*P]

    const int e   = blockIdx.y;
    const int i0  = blockIdx.x * 48;
    const int tid = threadIdx.x;
    const int w   = tid >> 5, lane = tid & 31;
    const int wm  = w >> 1, wn = w & 1;
    const int gr  = lane >> 2, tg = lane & 3;

    __shared__ int toks[128];
    if (tid < CAP)      toks[tid] = tok[e * CAP + tid];
    else if (tid < 128) toks[tid] = tok[e * CAP + CAP - 1];
    __syncthreads();

    const float* gwe = gw + ((size_t)e * NI + i0) * NH;
    const float* uwe = uw + ((size_t)e * NI + i0) * NH;

    float accg[2][3][4] = {};
    float accu[2][3][4] = {};

    const int NC = NH / 32;        // 64 chunks

    auto load_chunk = [&](int buf, int kc) {
        const int k0 = kc * 32;
        float* Ab = As + buf * 128 * P;
        float* Gb = Bg + buf * 48 * P;
        float* Ub = Bu + buf * 48 * P;
#pragma unroll
        for (int p = 0; p < 4; p++) {           // A: 128 rows x 8 f4
            int idx = tid + p * 256;
            int r = idx >> 3, c4 = (idx & 7) << 2;
            cp16(Ab + r * P + c4, hs + (size_t)toks[r] * NH + k0 + c4);
        }
#pragma unroll
        for (int p = 0; p < 3; p++) {           // Bg+Bu: 2 x 48 x 8 f4 = 768
            int idx = tid + p * 256;
            if (idx < 384) {
                int r = idx >> 3, c4 = (idx & 7) << 2;
                cp16(Gb + r * P + c4, gwe + (size_t)r * NH + k0 + c4);
            } else {
                int j = idx - 384;
                int r = j >> 3, c4 = (j & 7) << 2;
                cp16(Ub + r * P + c4, uwe + (size_t)r * NH + k0 + c4);
            }
        }
    };

    load_chunk(0, 0);
    cp_commit();

    int buf = 0;
    for (int kc = 0; kc < NC; kc++) {
        if (kc + 1 < NC) {
            load_chunk(buf ^ 1, kc + 1);
            cp_commit();
            cp_wait<1>();
        } else {
            cp_wait<0>();
        }
        __syncthreads();

        const float* A  = As + buf * 128 * P + wm * 32 * P;
        const float* BG = Bg + buf * 48 * P + wn * 24 * P;
        const float* BU = Bu + buf * 48 * P + wn * 24 * P;

#pragma unroll
        for (int ks = 0; ks < 2; ks++) {
            const int c0 = ks * 16 + 2 * tg;
            uint32_t a0[4], a1[4];
            a0[0] = pk(ld2(&A[(gr     ) * P + c0    ]));
            a0[1] = pk(ld2(&A[(gr +  8) * P + c0    ]));
            a0[2] = pk(ld2(&A[(gr     ) * P + c0 + 8]));
            a0[3] = pk(ld2(&A[(gr +  8) * P + c0 + 8]));
            a1[0] = pk(ld2(&A[(gr + 16) * P + c0    ]));
            a1[1] = pk(ld2(&A[(gr + 24) * P + c0    ]));
            a1[2] = pk(ld2(&A[(gr + 16) * P + c0 + 8]));
            a1[3] = pk(ld2(&A[(gr + 24) * P + c0 + 8]));
#pragma unroll
            for (int nt = 0; nt < 3; nt++) {
                uint32_t b[2];
                b[0] = pk(ld2(&BG[(nt * 8 + gr) * P + c0    ]));
                b[1] = pk(ld2(&BG[(nt * 8 + gr) * P + c0 + 8]));
                mma_f16(accg[0][nt], a0, b);
                mma_f16(accg[1][nt], a1, b);
                b[0] = pk(ld2(&BU[(nt * 8 + gr) * P + c0    ]));
                b[1] = pk(ld2(&BU[(nt * 8 + gr) * P + c0 + 8]));
                mma_f16(accu[0][nt], a0, b);
                mma_f16(accu[1][nt], a1, b);
            }
        }
        __syncthreads();
        buf ^= 1;
    }

    // Epilogue: h = silu(g)*u -> g_h (fp32)
#pragma unroll
    for (int mt = 0; mt < 2; mt++) {
#pragma unroll
        for (int half = 0; half < 2; half++) {
            const int r = wm * 32 + mt * 16 + gr + half * 8;
            if (r < CAP) {
                float* dst = g_h + ((size_t)e * CAP + r) * NI + i0 + wn * 24;
#pragma unroll
                for (int nt = 0; nt < 3; nt++) {
                    float g0 = accg[mt][nt][half * 2 + 0];
                    float g1 = accg[mt][nt][half * 2 + 1];
                    float u0 = accu[mt][nt][half * 2 + 0];
                    float u1 = accu[mt][nt][half * 2 + 1];
                    float2 hv = make_float2(silu(g0) * u0, silu(g1) * u1);
                    *(float2*)(dst + nt * 8 + 2 * tg) = hv;
                }
            }
        }
    }
}

// ---------------------------------------------------------------------------
// Kernel 2: down projection (fp16 MMA, fp32 smem, R7/R14-exact) -> g_o fp16
//   grid = (16 H-tiles of 128, NE). Block tile M=128 x N=128, K=192.
//   8 warps: 4 along M x 2 along N -> warp 32x64. 2 CTAs/SM.
// ---------------------------------------------------------------------------
__global__ __launch_bounds__(256, 2) void k_down(const float* __restrict__ dw /*[E,H,I]*/)
{
    extern __shared__ float smem[];
    float* As = smem;               // [2][128*P]
    float* Bs = As + 2 * 128 * P;   // [2][128*P]

    const int e   = blockIdx.y;
    const int h0  = blockIdx.x * 128;
    const int tid = threadIdx.x;
    const int w   = tid >> 5, lane = tid & 31;
    const int wm  = w >> 1, wn = w & 1;
    const int gr  = lane >> 2, tg = lane & 3;

    const float* hsrc = g_h + (size_t)e * CAP * NI;
    const float* dwe  = dw + ((size_t)e * NH + h0) * NI;

    float acc[2][8][4] = {};

    const int NC = NI / 32;    // 6 chunks

    auto load_chunk = [&](int buf, int kc) {
        const int k0 = kc * 32;
        float* Ab = As + buf * 128 * P;
        float* Bb = Bs + buf * 128 * P;
#pragma unroll
        for (int p = 0; p < 4; p++) {           // A: 128 x 8 f4 (rows>=CAP clamped)
            int idx = tid + p * 256;
            int r = idx >> 3, c4 = (idx & 7) << 2;
            int rr = r < CAP ? r : CAP - 1;
            cp16(Ab + r * P + c4, hsrc + (size_t)rr * NI + k0 + c4);
        }
#pragma unroll
        for (int p = 0; p < 4; p++) {           // B: 128 x 8 f4
            int idx = tid + p * 256;
            int r = idx >> 3, c4 = (idx & 7) << 2;
            cp16(Bb + r * P + c4, dwe + (size_t)r * NI + k0 + c4);
        }
    };

    load_chunk(0, 0);
    cp_commit();

    int buf = 0;
    for (int kc = 0; kc < NC; kc++) {
        if (kc + 1 < NC) {
            load_chunk(buf ^ 1, kc + 1);
            cp_commit();
            cp_wait<1>();
        } else {
            cp_wait<0>();
        }
        __syncthreads();

        const float* A = As + buf * 128 * P + wm * 32 * P;
        const float* B = Bs + buf * 128 * P + wn * 64 * P;

#pragma unroll
        for (int ks = 0; ks < 2; ks++) {
            const int c0 = ks * 16 + 2 * tg;
            uint32_t a0[4], a1[4];
            a0[0] = pk(ld2(&A[(gr     ) * P + c0    ]));
            a0[1] = pk(ld2(&A[(gr +  8) * P + c0    ]));
            a0[2] = pk(ld2(&A[(gr     ) * P + c0 + 8]));
            a0[3] = pk(ld2(&A[(gr +  8) * P + c0 + 8]));
            a1[0] = pk(ld2(&A[(gr + 16) * P + c0    ]));
            a1[1] = pk(ld2(&A[(gr + 24) * P + c0    ]));
            a1[2] = pk(ld2(&A[(gr + 16) * P + c0 + 8]));
            a1[3] = pk(ld2(&A[(gr + 24) * P + c0 + 8]));
#pragma unroll
            for (int nt = 0; nt < 8; nt++) {
                uint32_t b[2];
                b[0] = pk(ld2(&B[(nt * 8 + gr) * P + c0    ]));
                b[1] = pk(ld2(&B[(nt * 8 + gr) * P + c0 + 8]));
                mma_f16(acc[0][nt], a0, b);
                mma_f16(acc[1][nt], a1, b);
            }
        }
        __syncthreads();
        buf ^= 1;
    }

    // Epilogue -> g_o (fp16)
#pragma unroll
    for (int mt = 0; mt < 2; mt++) {
#pragma unroll
        for (int half = 0; half < 2; half++) {
            const int r = wm * 32 + mt * 16 + gr + half * 8;
            if (r < CAP) {
                __half* dst = g_o + ((size_t)e * CAP + r) * NH + h0 + wn * 64;
#pragma unroll
                for (int nt = 0; nt < 8; nt++) {
                    *(__half2*)(dst + nt * 8 + 2 * tg) =
                        __floats2half2_rn(acc[mt][nt][half * 2 + 0],
                                          acc[mt][nt][half * 2 + 1]);
                }
            }
        }
    }
}

// ---------------------------------------------------------------------------
// Kernel 3: permute-gather + top-k weighted combine + shared expert
// ---------------------------------------------------------------------------
__global__ __launch_bounds__(256) void k_combine(
    const int*   __restrict__ rei,  // [K*S]
    const float* __restrict__ tw,   // [K,S,1]
    const float* __restrict__ sh,   // [1,S,H]
    float*       __restrict__ out)  // [1,S,H]
{
    const int s = blockIdx.x;
    __shared__ int   rows[NK];
    __shared__ float wts[NK];
    if (threadIdx.x < NK) {
        rows[threadIdx.x] = rei[threadIdx.x * NS + s];
        wts[threadIdx.x]  = tw[threadIdx.x * NS + s];
    }
    __syncthreads();

    for (int h = threadIdx.x * 4; h < NH; h += 256 * 4) {
        float4 a = *(const float4*)(sh + (size_t)s * NH + h);
#pragma unroll
        for (int k = 0; k < NK; k++) {
            const __half* src = g_o + (size_t)rows[k] * NH + h;
            float2 f01 = __half22float2(*(const __half2*)(src));
            float2 f23 = __half22float2(*(const __half2*)(src + 2));
            const float wv = wts[k];
            a.x = fmaf(wv, f01.x, a.x);
            a.y = fmaf(wv, f01.y, a.y);
            a.z = fmaf(wv, f23.x, a.z);
            a.w = fmaf(wv, f23.y, a.w);
        }
        *(float4*)(out + (size_t)s * NH + h) = a;
    }
}

// ---------------------------------------------------------------------------
extern "C" void kernel_launch(void* const* d_in, const int* in_sizes, int n_in,
                              void* d_out, int out_size)
{
    const float* hs  = (const float*)d_in[0];
    const int*   tok = (const int*)  d_in[1];
    const int*   rei = (const int*)  d_in[2];
    const float* tw  = (const float*)d_in[3];
    const float* sh  = (const float*)d_in[4];
    const float* gw  = (const float*)d_in[5];
    const float* uw  = (const float*)d_in[6];
    const float* dw  = (const float*)d_in[7];
    float* out = (float*)d_out;

    const int smem1 = 2 * (128 + 48 + 48) * P * 4;   // 71680 B
    const int smem2 = 2 * (128 + 128) * P * 4;       // 81920 B
    cudaFuncSetAttribute(k_gateup, cudaFuncAttributeMaxDynamicSharedMemorySize, smem1);
    cudaFuncSetAttribute(k_down,   cudaFuncAttributeMaxDynamicSharedMemorySize, smem2);

    dim3 g1(4, NE);         // 640 blocks
    k_gateup<<<g1, 256, smem1>>>(hs, tok, gw, uw);

    dim3 g2(NH / 128, NE);  // 2560 blocks
    k_down<<<g2, 256, smem2>>>(dw);

    k_combine<<<NS, 256>>>(rei, tw, sh, out);
}

// round 17
// speedup vs baseline: 1.4373x; 1.0206x over previous
#include <cuda_runtime.h>
#include <cuda_fp16.h>
#include <math.h>
#include <stdint.h>

// Problem constants
#define NE  160     // experts
#define CAP 120     // capacity per expert
#define NS  3200    // sequence length
#define NH  2048    // hidden dim
#define NI  192     // ffn dim per device
#define NK  6       // top-k

#define P   40      // fp32 smem pitch (floats); LDS.64 frag loads conflict-free
#define PB  80      // fp16 smem pitch (bytes); ldmatrix rows cover all 32 banks

// Scratch: h fp16 (same rounding gateup's MMA feed already applied), o fp16
__device__ __half g_h[(size_t)NE * CAP * NI];   // 7.4 MB
__device__ __half g_o[(size_t)NE * CAP * NH];   // 79  MB

// ---------------------------------------------------------------------------
// helpers
// ---------------------------------------------------------------------------
__device__ __forceinline__ uint32_t s2u(const void* p) {
    uint32_t a;
    asm("{ .reg .u64 t; cvta.to.shared.u64 t, %1; cvt.u32.u64 %0, t; }" : "=r"(a) : "l"(p));
    return a;
}
__device__ __forceinline__ void cp16(float* smem_dst, const float* gsrc) {
    uint32_t sa = (uint32_t)__cvta_generic_to_shared(smem_dst);
    // .cg: L2-only. All tiles are streaming (zero reuse) -> keep L1 clean.
    asm volatile("cp.async.cg.shared.global [%0], [%1], 16;" :: "r"(sa), "l"(gsrc));
}
__device__ __forceinline__ void cp16s(uint32_t sa, const void* g) {
    asm volatile("cp.async.cg.shared.global [%0], [%1], 16;" :: "r"(sa), "l"(g));
}
__device__ __forceinline__ void cp_commit() { asm volatile("cp.async.commit_group;"); }
template<int N> __device__ __forceinline__ void cp_wait() {
    asm volatile("cp.async.wait_group %0;" :: "n"(N));
}
// pack float2 {lo,hi} -> f16x2 (lo in low 16 bits)
__device__ __forceinline__ uint32_t pk(float2 v) {
    uint32_t r;
    asm("cvt.rn.f16x2.f32 %0, %1, %2;" : "=r"(r) : "f"(v.y), "f"(v.x));
    return r;
}
__device__ __forceinline__ void ldm_x4(uint32_t* r, uint32_t a) {
    asm volatile("ldmatrix.sync.aligned.m8n8.x4.shared.b16 {%0,%1,%2,%3}, [%4];"
                 : "=r"(r[0]), "=r"(r[1]), "=r"(r[2]), "=r"(r[3]) : "r"(a));
}
__device__ __forceinline__ void mma_f16(float* c, const uint32_t* a, const uint32_t* b) {
    asm volatile(
        "mma.sync.aligned.m16n8k16.row.col.f32.f16.f16.f32 "
        "{%0,%1,%2,%3},{%4,%5,%6,%7},{%8,%9},{%0,%1,%2,%3};"
        : "+f"(c[0]), "+f"(c[1]), "+f"(c[2]), "+f"(c[3])
        : "r"(a[0]), "r"(a[1]), "r"(a[2]), "r"(a[3]), "r"(b[0]), "r"(b[1]));
}
__device__ __forceinline__ float silu(float g) { return g / (1.f + __expf(-g)); }
__device__ __forceinline__ float2 ld2(const float* p) { return *(const float2*)p; }

// ---------------------------------------------------------------------------
// Kernel 1: gathered gate/up GEMM (fp16 MMA, fp32 accum) + fused SiLU
//   R16-exact geometry: grid (4 I-tiles of 48, NE), 256 thr (8 warps wm4xwn2),
//   block tile M=128 x N=48 for BOTH gate and up, K chunk 32 (2 k16 steps),
//   2-stage cp.async(.cg) pipeline, 2 CTAs/SM. Epilogue now writes fp16 g_h.
// ---------------------------------------------------------------------------
__global__ __launch_bounds__(256, 2) void k_gateup(
    const float* __restrict__ hs,   // [S,H]
    const int*   __restrict__ tok,  // [E,CAP]
    const float* __restrict__ gw,   // [E,I,H]
    const float* __restrict__ uw)   // [E,I,H]
{
    extern __shared__ float smem[];
    float* As = smem;               // [2][128*P]
    float* Bg = As + 2 * 128 * P;   // [2][48*P]
    float* Bu = Bg + 2 * 48 * P;    // [2][48*P]

    const int e   = blockIdx.y;
    const int i0  = blockIdx.x * 48;
    const int tid = threadIdx.x;
    const int w   = tid >> 5, lane = tid & 31;
    const int wm  = w >> 1, wn = w & 1;
    const int gr  = lane >> 2, tg = lane & 3;

    __shared__ int toks[128];
    if (tid < CAP)      toks[tid] = tok[e * CAP + tid];
    else if (tid < 128) toks[tid] = tok[e * CAP + CAP - 1];
    __syncthreads();

    const float* gwe = gw + ((size_t)e * NI + i0) * NH;
    const float* uwe = uw + ((size_t)e * NI + i0) * NH;

    float accg[2][3][4] = {};
    float accu[2][3][4] = {};

    const int NC = NH / 32;        // 64 chunks

    auto load_chunk = [&](int buf, int kc) {
        const int k0 = kc * 32;
        float* Ab = As + buf * 128 * P;
        float* Gb = Bg + buf * 48 * P;
        float* Ub = Bu + buf * 48 * P;
#pragma unroll
        for (int p = 0; p < 4; p++) {           // A: 128 rows x 8 f4
            int idx = tid + p * 256;
            int r = idx >> 3, c4 = (idx & 7) << 2;
            cp16(Ab + r * P + c4, hs + (size_t)toks[r] * NH + k0 + c4);
        }
#pragma unroll
        for (int p = 0; p < 3; p++) {           // Bg+Bu: 2 x 48 x 8 f4 = 768
            int idx = tid + p * 256;
            if (idx < 384) {
                int r = idx >> 3, c4 = (idx & 7) << 2;
                cp16(Gb + r * P + c4, gwe + (size_t)r * NH + k0 + c4);
            } else {
                int j = idx - 384;
                int r = j >> 3, c4 = (j & 7) << 2;
                cp16(Ub + r * P + c4, uwe + (size_t)r * NH + k0 + c4);
            }
        }
    };

    load_chunk(0, 0);
    cp_commit();

    int buf = 0;
    for (int kc = 0; kc < NC; kc++) {
        if (kc + 1 < NC) {
            load_chunk(buf ^ 1, kc + 1);
            cp_commit();
            cp_wait<1>();
        } else {
            cp_wait<0>();
        }
        __syncthreads();

        const float* A  = As + buf * 128 * P + wm * 32 * P;
        const float* BG = Bg + buf * 48 * P + wn * 24 * P;
        const float* BU = Bu + buf * 48 * P + wn * 24 * P;

#pragma unroll
        for (int ks = 0; ks < 2; ks++) {
            const int c0 = ks * 16 + 2 * tg;
            uint32_t a0[4], a1[4];
            a0[0] = pk(ld2(&A[(gr     ) * P + c0    ]));
            a0[1] = pk(ld2(&A[(gr +  8) * P + c0    ]));
            a0[2] = pk(ld2(&A[(gr     ) * P + c0 + 8]));
            a0[3] = pk(ld2(&A[(gr +  8) * P + c0 + 8]));
            a1[0] = pk(ld2(&A[(gr + 16) * P + c0    ]));
            a1[1] = pk(ld2(&A[(gr + 24) * P + c0    ]));
            a1[2] = pk(ld2(&A[(gr + 16) * P + c0 + 8]));
            a1[3] = pk(ld2(&A[(gr + 24) * P + c0 + 8]));
#pragma unroll
            for (int nt = 0; nt < 3; nt++) {
                uint32_t b[2];
                b[0] = pk(ld2(&BG[(nt * 8 + gr) * P + c0    ]));
                b[1] = pk(ld2(&BG[(nt * 8 + gr) * P + c0 + 8]));
                mma_f16(accg[0][nt], a0, b);
                mma_f16(accg[1][nt], a1, b);
                b[0] = pk(ld2(&BU[(nt * 8 + gr) * P + c0    ]));
                b[1] = pk(ld2(&BU[(nt * 8 + gr) * P + c0 + 8]));
                mma_f16(accu[0][nt], a0, b);
                mma_f16(accu[1][nt], a1, b);
            }
        }
        __syncthreads();
        buf ^= 1;
    }

    // Epilogue: h = silu(g)*u -> g_h (fp16; same rounding the MMA feed applies)
#pragma unroll
    for (int mt = 0; mt < 2; mt++) {
#pragma unroll
        for (int half = 0; half < 2; half++) {
            const int r = wm * 32 + mt * 16 + gr + half * 8;
            if (r < CAP) {
                __half* dst = g_h + ((size_t)e * CAP + r) * NI + i0 + wn * 24;
#pragma unroll
                for (int nt = 0; nt < 3; nt++) {
                    float g0 = accg[mt][nt][half * 2 + 0];
                    float g1 = accg[mt][nt][half * 2 + 1];
                    float u0 = accu[mt][nt][half * 2 + 0];
                    float u1 = accu[mt][nt][half * 2 + 1];
                    *(__half2*)(dst + nt * 8 + 2 * tg) =
                        __floats2half2_rn(silu(g0) * u0, silu(g1) * u1);
                }
            }
        }
    }
}

// ---------------------------------------------------------------------------
// Kernel 2: down projection -> g_o fp16
//   A (g_h fp16) streamed via cp.async + ldmatrix (R8/R11-validated layout);
//   B (down_w fp32) streamed via cp.async + pk fragments (R16-exact).
//   grid = (16 H-tiles of 128, NE). Block tile M=128 x N=128, K=192.
//   8 warps: 4 along M x 2 along N -> warp 32x64. 2 CTAs/SM.
// ---------------------------------------------------------------------------
__global__ __launch_bounds__(256, 2) void k_down(const float* __restrict__ dw /*[E,H,I]*/)
{
    extern __shared__ float smem[];
    const uint32_t sA = s2u(smem);               // [2][128*PB] fp16 = 20480 B
    float* Bs = (float*)((char*)smem + 20480);   // [2][128*P] fp32 = 40960 B

    const int e   = blockIdx.y;
    const int h0  = blockIdx.x * 128;
    const int tid = threadIdx.x;
    const int w   = tid >> 5, lane = tid & 31;
    const int wm  = w >> 1, wn = w & 1;
    const int gr  = lane >> 2, tg = lane & 3;
    const int lrow = lane & 7, lsel = lane >> 3;

    const __half* hsrc = g_h + (size_t)e * CAP * NI;
    const float*  dwe  = dw + ((size_t)e * NH + h0) * NI;

    float acc[2][8][4] = {};

    const int NC = NI / 32;    // 6 chunks

    auto load_chunk = [&](int buf, int kc) {
        const int k0 = kc * 32;
        const uint32_t Ab = sA + buf * 128 * PB;
        float* Bb = Bs + buf * 128 * P;
#pragma unroll
        for (int p = 0; p < 2; p++) {           // A: 128 rows x 4 x 16B (fp16)
            int idx = tid + p * 256;            // 512 total
            int r = idx >> 2, c = idx & 3;
            int rr = r < CAP ? r : CAP - 1;
            cp16s(Ab + r * PB + c * 16, hsrc + (size_t)rr * NI + k0 + c * 8);
        }
#pragma unroll
        for (int p = 0; p < 4; p++) {           // B: 128 x 8 f4 (fp32)
            int idx = tid + p * 256;
            int r = idx >> 3, c4 = (idx & 7) << 2;
            cp16(Bb + r * P + c4, dwe + (size_t)r * NI + k0 + c4);
        }
    };

    // A ldmatrix lane offset (bytes within a chunk-tile), R8/R11-validated:
    // lsel 0/1 -> rows m0-7/m8-15 (k0-7), lsel 2/3 -> same rows, k8-15 (+16B)
    const uint32_t aoff = (uint32_t)((wm * 32 + lrow + ((lsel & 1) << 3)) * PB
                                     + ((lsel >> 1) << 4));

    load_chunk(0, 0);
    cp_commit();

    int buf = 0;
    for (int kc = 0; kc < NC; kc++) {
        if (kc + 1 < NC) {
            load_chunk(buf ^ 1, kc + 1);
            cp_commit();
            cp_wait<1>();
        } else {
            cp_wait<0>();
        }
        __syncthreads();

        const uint32_t Ab = sA + buf * 128 * PB;
        const float* B = Bs + buf * 128 * P + wn * 64 * P;

#pragma unroll
        for (int ks = 0; ks < 2; ks++) {
            const uint32_t kb = (uint32_t)(ks * 32);   // 16 halves = 32 bytes
            const int c0 = ks * 16 + 2 * tg;
            uint32_t a0[4], a1[4];
            ldm_x4(a0, Ab + aoff + kb);
            ldm_x4(a1, Ab + aoff + 16 * PB + kb);
#pragma unroll
            for (int nt = 0; nt < 8; nt++) {
                uint32_t b[2];
                b[0] = pk(ld2(&B[(nt * 8 + gr) * P + c0    ]));
                b[1] = pk(ld2(&B[(nt * 8 + gr) * P + c0 + 8]));
                mma_f16(acc[0][nt], a0, b);
                mma_f16(acc[1][nt], a1, b);
            }
        }
        __syncthreads();
        buf ^= 1;
    }

    // Epilogue -> g_o (fp16)
#pragma unroll
    for (int mt = 0; mt < 2; mt++) {
#pragma unroll
        for (int half = 0; half < 2; half++) {
            const int r = wm * 32 + mt * 16 + gr + half * 8;
            if (r < CAP) {
                __half* dst = g_o + ((size_t)e * CAP + r) * NH + h0 + wn * 64;
#pragma unroll
                for (int nt = 0; nt < 8; nt++) {
                    *(__half2*)(dst + nt * 8 + 2 * tg) =
                        __floats2half2_rn(acc[mt][nt][half * 2 + 0],
                                          acc[mt][nt][half * 2 + 1]);
                }
            }
        }
    }
}

// ---------------------------------------------------------------------------
// Kernel 3: permute-gather + top-k weighted combine + shared expert
// ---------------------------------------------------------------------------
__global__ __launch_bounds__(256) void k_combine(
    const int*   __restrict__ rei,  // [K*S]
    const float* __restrict__ tw,   // [K,S,1]
    const float* __restrict__ sh,   // [1,S,H]
    float*       __restrict__ out)  // [1,S,H]
{
    const int s = blockIdx.x;
    __shared__ int   rows[NK];
    __shared__ float wts[NK];
    if (threadIdx.x < NK) {
        rows[threadIdx.x] = rei[threadIdx.x * NS + s];
        wts[threadIdx.x]  = tw[threadIdx.x * NS + s];
    }
    __syncthreads();

    for (int h = threadIdx.x * 4; h < NH; h += 256 * 4) {
        float4 a = *(const float4*)(sh + (size_t)s * NH + h);
#pragma unroll
        for (int k = 0; k < NK; k++) {
            const __half* src = g_o + (size_t)rows[k] * NH + h;
            float2 f01 = __half22float2(*(const __half2*)(src));
            float2 f23 = __half22float2(*(const __half2*)(src + 2));
            const float wv = wts[k];
            a.x = fmaf(wv, f01.x, a.x);
            a.y = fmaf(wv, f01.y, a.y);
            a.z = fmaf(wv, f23.x, a.z);
            a.w = fmaf(wv, f23.y, a.w);
        }
        *(float4*)(out + (size_t)s * NH + h) = a;
    }
}

// ---------------------------------------------------------------------------
extern "C" void kernel_launch(void* const* d_in, const int* in_sizes, int n_in,
                              void* d_out, int out_size)
{
    const float* hs  = (const float*)d_in[0];
    const int*   tok = (const int*)  d_in[1];
    const int*   rei = (const int*)  d_in[2];
    const float* tw  = (const float*)d_in[3];
    const float* sh  = (const float*)d_in[4];
    const float* gw  = (const float*)d_in[5];
    const float* uw  = (const float*)d_in[6];
    const float* dw  = (const float*)d_in[7];
    float* out = (float*)d_out;

    const int smem1 = 2 * (128 + 48 + 48) * P * 4;   // 71680 B
    const int smem2 = 2 * 128 * PB + 2 * 128 * P * 4; // 20480 + 40960 = 61440 B
    cudaFuncSetAttribute(k_gateup, cudaFuncAttributeMaxDynamicSharedMemorySize, smem1);
    cudaFuncSetAttribute(k_down,   cudaFuncAttributeMaxDynamicSharedMemorySize, smem2);

    dim3 g1(4, NE);         // 640 blocks
    k_gateup<<<g1, 256, smem1>>>(hs, tok, gw, uw);

    dim3 g2(NH / 128, NE);  // 2560 blocks
    k_down<<<g2, 256, smem2>>>(dw);

    k_combine<<<NS, 256>>>(rei, tw, sh, out);
}